// round 1
// baseline (speedup 1.0000x reference)
#include <cuda_runtime.h>
#include <math.h>

// Entire reference reduces to: out = 1.0 + gelu(bn(conv3x3_groups2(x4, local_w)))
// (attention branch is exactly 1.0: softmax over a size-1 axis -> ones,
//  then attn @ ones = softmax row sums = 1).

#define NPW 24
#define NPOS 576           // 24*24
#define ICG 64             // input channels per group
#define OCB 8              // output channels per block
#define RB 6               // output rows per block
#define THREADS 192
#define SMEM_X (ICG*8*NPW)       // 64 ch * 8 rows (6 + 2 halo) * 24 w = 12288 floats
#define SMEM_W (ICG*9*OCB)       // 4608 floats, layout [ic][k][oc]
#define SMEM_BYTES ((SMEM_X + SMEM_W)*4)   // 67584 bytes

__global__ __launch_bounds__(THREADS)
void fused_c_kernel(const float* __restrict__ x,    // (2, 73728) flat
                    const float* __restrict__ lw,   // (128, 64, 3, 3)
                    const float* __restrict__ gma,  // (128,)
                    const float* __restrict__ bta,  // (128,)
                    float* __restrict__ out)        // (2, 73728) flat
{
    extern __shared__ float sm[];
    float* sX = sm;            // [ic][r(8)][w(24)]
    float* sW = sm + SMEM_X;   // [ic][k(9)][o(8)]

    int bid = blockIdx.x;
    int ht  = bid & 3;  bid >>= 2;   // 4 row tiles of 6
    int occ = bid & 7;  bid >>= 3;   // 8 oc chunks of 8
    int g   = bid & 1;
    int b   = bid >> 1;

    const int h0 = ht * RB;
    const int ocBase = g * 64 + occ * OCB;
    const int tid = threadIdx.x;

    // ---- stage input tile (rows h0-1 .. h0+6), vectorized float4 ----
    const float* xb = x + b * (128 * NPOS) + (g * ICG) * NPOS;
    #pragma unroll 4
    for (int i4 = tid; i4 < ICG * 8 * 6; i4 += THREADS) {   // 3072 float4
        int ic  = i4 / 48;
        int rem = i4 - ic * 48;
        int r   = rem / 6;
        int w4  = rem - r * 6;
        int h   = h0 - 1 + r;
        float4 v = make_float4(0.f, 0.f, 0.f, 0.f);
        if ((unsigned)h < 24u)
            v = *reinterpret_cast<const float4*>(xb + ic * NPOS + h * NPW + w4 * 4);
        reinterpret_cast<float4*>(sX)[i4] = v;
    }

    // ---- stage weights, transposed to [ic][k][oc] (bank-friendly) ----
    const float* wb = lw + ocBase * (ICG * 9);
    #pragma unroll 4
    for (int i = tid; i < OCB * ICG * 9; i += THREADS) {
        int o   = i / (ICG * 9);
        int rem = i - o * (ICG * 9);
        int ic  = rem / 9;
        int k   = rem - ic * 9;
        sW[(ic * 9 + k) * OCB + o] = wb[i];
    }
    __syncthreads();

    // ---- compute: thread = (oc_local, w), 6 output rows ----
    const int w = tid % NPW;
    const int o = tid / NPW;     // 0..7

    float acc[RB];
    #pragma unroll
    for (int r = 0; r < RB; r++) acc[r] = 0.f;

    #pragma unroll 2
    for (int ic = 0; ic < ICG; ic++) {
        const float* xr = sX + ic * (8 * NPW);
        const float* wr = sW + ic * 9 * OCB + o;

        float wk[9];
        #pragma unroll
        for (int k = 0; k < 9; k++) wk[k] = wr[k * OCB];

        float xm[8], xc[8], xp[8];
        #pragma unroll
        for (int r = 0; r < 8; r++) {
            const float* row = xr + r * NPW;
            xc[r] = row[w];
            xm[r] = (w > 0)  ? row[w - 1] : 0.f;
            xp[r] = (w < 23) ? row[w + 1] : 0.f;
        }

        #pragma unroll
        for (int r = 0; r < RB; r++) {
            #pragma unroll
            for (int kh = 0; kh < 3; kh++) {
                int rr = r + kh;
                acc[r] += wk[kh * 3 + 0] * xm[rr];
                acc[r] += wk[kh * 3 + 1] * xc[rr];
                acc[r] += wk[kh * 3 + 2] * xp[rr];
            }
        }
    }

    // ---- epilogue: BN affine + exact GELU + 1.0 ----
    const int oc = ocBase + o;
    const float ge = gma[oc] * 0.9999950000374997f;  // gamma / sqrt(1 + 1e-5)
    const float be = bta[oc];
    float* ob = out + b * (128 * NPOS) + oc * NPOS + h0 * NPW + w;
    #pragma unroll
    for (int r = 0; r < RB; r++) {
        float y = acc[r] * ge + be;
        float gel = 0.5f * y * (1.0f + erff(y * 0.70710678118654752f));
        ob[r * NPW] = 1.0f + gel;
    }
}

extern "C" void kernel_launch(void* const* d_in, const int* in_sizes, int n_in,
                              void* d_out, int out_size)
{
    const float* x   = (const float*)d_in[0];
    const float* lw  = (const float*)d_in[9];   // local_w
    const float* gma = (const float*)d_in[10];  // bnc1_gamma
    const float* bta = (const float*)d_in[11];  // bnc1_beta
    float* out = (float*)d_out;

    cudaFuncSetAttribute(fused_c_kernel,
                         cudaFuncAttributeMaxDynamicSharedMemorySize, SMEM_BYTES);
    fused_c_kernel<<<128, THREADS, SMEM_BYTES>>>(x, lw, gma, bta, out);
}